// round 12
// baseline (speedup 1.0000x reference)
#include <cuda_runtime.h>
#include <cuda_bf16.h>
#include <math.h>
#include <stdint.h>

typedef __nv_bfloat16 bf16;

// Problem constants
#define Bb 2
#define Nn 2048
#define Dd 1024
#define Ee 8
#define Hh 2048
#define Kk 2
#define Tt (Bb*Nn)              // 4096 tokens
#define SLOTS (Tt*Kk)           // 8192

// ---------------- routing state ----------------------------------------------
__device__ int   g_count[Ee];
__device__ int   g_off[Ee];
__device__ float g_ent;
__device__ int   g_tok[Ee * Tt];
__device__ int   g_pos[Tt * Kk];
__device__ int   g_eidx[Tt * Kk];
__device__ float g_gatev[Tt * Kk];

// ---------------- bf16 split planes (weights stay in ORIGINAL layout) --------
__device__ bf16  g_xh[(size_t)Tt * Dd],      g_xl[(size_t)Tt * Dd];
__device__ bf16  g_w1h[(size_t)Ee * Dd * Hh], g_w1l[(size_t)Ee * Dd * Hh]; // [E][D][H] row-major
__device__ bf16  g_w2h[(size_t)Ee * Hh * Dd], g_w2l[(size_t)Ee * Hh * Dd]; // [E][H][D] row-major
__device__ bf16  g_hh[(size_t)SLOTS * Hh],   g_hl[(size_t)SLOTS * Hh];
__device__ float g_y[(size_t)SLOTS * Dd];

// ---------------- persistent-kernel scheduling state --------------------------
#define MBMAX 32
#define NB1 (Hh/256)            // 8
#define NB2 (Dd/256)            // 4
#define TCX 64                  // conv_x tickets (65536 floats each)
#define TW1E 32                 // conv w1 tickets per expert
#define TW2E 32
#define TB1 TCX                                   // 64
#define TB2 (TB1 + Ee*TW1E)                       // 320
#define TB3 (TB2 + Ee*TW2E)                       // 576
#define TB4 (TB3 + Ee*MBMAX*NB1)                  // 2624
#define TEND (TB4 + Ee*MBMAX*NB2)                 // 3648

__device__ int g_ticket;
__device__ int c_x;
__device__ int c_w1[Ee], c_w2[Ee];
__device__ int c_h[Ee * MBMAX];

// ============================ PTX helpers ====================================
__device__ __forceinline__ uint32_t smem_u32(const void* p) {
    uint32_t a;
    asm("{ .reg .u64 t; cvta.to.shared.u64 t, %1; cvt.u32.u64 %0, t; }"
        : "=r"(a) : "l"(p));
    return a;
}
__device__ __forceinline__ void cp16(uint32_t dst, const void* src, int sz) {
    asm volatile("cp.async.cg.shared.global [%0], [%1], 16, %2;"
                 :: "r"(dst), "l"(src), "r"(sz) : "memory");
}
__device__ __forceinline__ void cp_commit() {
    asm volatile("cp.async.commit_group;" ::: "memory");
}
__device__ __forceinline__ void cp_wait1() {
    asm volatile("cp.async.wait_group 1;" ::: "memory");
}
__device__ __forceinline__ void cp_wait0() {
    asm volatile("cp.async.wait_group 0;" ::: "memory");
}
__device__ __forceinline__ void ldsm4(uint32_t* r, uint32_t addr) {
    asm volatile("ldmatrix.sync.aligned.m8n8.x4.shared.b16 {%0,%1,%2,%3}, [%4];"
                 : "=r"(r[0]), "=r"(r[1]), "=r"(r[2]), "=r"(r[3]) : "r"(addr));
}
__device__ __forceinline__ void ldsm4t(uint32_t* r, uint32_t addr) {
    asm volatile("ldmatrix.sync.aligned.m8n8.x4.trans.shared.b16 {%0,%1,%2,%3}, [%4];"
                 : "=r"(r[0]), "=r"(r[1]), "=r"(r[2]), "=r"(r[3]) : "r"(addr));
}
__device__ __forceinline__ void mma16816(float* c, const uint32_t* a, const uint32_t* b) {
    asm volatile(
        "mma.sync.aligned.m16n8k16.row.col.f32.bf16.bf16.f32 "
        "{%0,%1,%2,%3}, {%4,%5,%6,%7}, {%8,%9}, {%0,%1,%2,%3};"
        : "+f"(c[0]), "+f"(c[1]), "+f"(c[2]), "+f"(c[3])
        : "r"(a[0]), "r"(a[1]), "r"(a[2]), "r"(a[3]), "r"(b[0]), "r"(b[1]));
}
__device__ __forceinline__ int ldacq(const int* p) {
    int v;
    asm volatile("ld.acquire.gpu.b32 %0, [%1];" : "=r"(v) : "l"(p) : "memory");
    return v;
}

// A smem tile: 128 rows x 8 chunks of 16B (64 bf16/row), XOR-swizzled
__device__ __forceinline__ uint32_t swA(int row, int ch) {
    return (uint32_t)((row * 8 + (ch ^ (row & 7))) << 4);
}
// B smem tile (row-major K x N): 64 rows x 32 chunks of 16B (256 bf16/row)
__device__ __forceinline__ uint32_t swB(int row, int ch) {
    return (uint32_t)((row * 32 + ((ch & 24) | ((ch ^ row) & 7))) << 4);
}

// dynamic smem: [0,512) toks; per stage 96KB = AH 16K | AL 16K | BH 32K | BL 32K
#define SM_AH(st) (1024 + (st) * 98304)
#define SM_AL(st) (1024 + (st) * 98304 + 16384)
#define SM_BH(st) (1024 + (st) * 98304 + 32768)
#define SM_BL(st) (1024 + (st) * 98304 + 65536)
#define MMA_SMEM_BYTES (1024 + 2 * 98304)   // 197632

// ---------------- reset -------------------------------------------------------
__global__ void reset_kernel() {
    int i = threadIdx.x;
    if (i < Ee) { g_count[i] = 0; c_w1[i] = 0; c_w2[i] = 0; }
    if (i == 0) { g_ent = 0.0f; g_ticket = 0; c_x = 0; }
    if (i < Ee * MBMAX) c_h[i] = 0;
}

// ---------------- gating: one warp per token ---------------------------------
__global__ void gate_kernel(const float* __restrict__ x,
                            const float* __restrict__ wg,
                            const float* __restrict__ bg) {
    int t    = (blockIdx.x * blockDim.x + threadIdx.x) >> 5;
    int lane = threadIdx.x & 31;
    if (t >= Tt) return;

    const float* xr = x + (size_t)t * Dd;
    float acc[Ee];
    #pragma unroll
    for (int e = 0; e < Ee; e++) acc[e] = 0.0f;

    for (int d = lane; d < Dd; d += 32) {
        float xv = xr[d];
        const float4* w4 = (const float4*)(wg + (size_t)d * Ee);
        float4 a = w4[0], b = w4[1];
        acc[0] += xv * a.x; acc[1] += xv * a.y; acc[2] += xv * a.z; acc[3] += xv * a.w;
        acc[4] += xv * b.x; acc[5] += xv * b.y; acc[6] += xv * b.z; acc[7] += xv * b.w;
    }
    #pragma unroll
    for (int e = 0; e < Ee; e++) {
        #pragma unroll
        for (int off = 16; off; off >>= 1)
            acc[e] += __shfl_xor_sync(0xffffffffu, acc[e], off);
    }

    if (lane == 0) {
        float best0 = -INFINITY, best1 = -INFINITY;
        int i0 = 0, i1 = 0;
        #pragma unroll
        for (int e = 0; e < Ee; e++) {
            float l = acc[e] + bg[e];
            if (l > best0)      { best1 = best0; i1 = i0; best0 = l; i0 = e; }
            else if (l > best1) { best1 = l; i1 = e; }
        }
        float ex = expf(best1 - best0);
        float g0 = 1.0f / (1.0f + ex);
        float g1 = ex * g0;
        float ent = -(g0 * logf(fmaxf(g0, 1e-8f)) + g1 * logf(fmaxf(g1, 1e-8f)));
        atomicAdd(&g_ent, ent);

        int p0 = atomicAdd(&g_count[i0], 1);
        g_tok[i0 * Tt + p0] = t;
        g_pos[t * Kk + 0]   = p0;
        g_gatev[t * Kk + 0] = g0;
        g_eidx[t * Kk + 0]  = i0;

        int p1 = atomicAdd(&g_count[i1], 1);
        g_tok[i1 * Tt + p1] = t;
        g_pos[t * Kk + 1]   = p1;
        g_gatev[t * Kk + 1] = g1;
        g_eidx[t * Kk + 1]  = i1;
    }
}

__global__ void offs_kernel() {
    if (threadIdx.x == 0) {
        int a = 0;
        #pragma unroll
        for (int e = 0; e < Ee; e++) { g_off[e] = a; a += g_count[e]; }
    }
}

// ---------------- elementwise fp32 -> bf16 hi/lo ------------------------------
__device__ __forceinline__ unsigned pack2(float a, float b) {
    bf16 ha = __float2bfloat16(a), hb = __float2bfloat16(b);
    return (unsigned)__bfloat16_as_ushort(ha)
         | ((unsigned)__bfloat16_as_ushort(hb) << 16);
}

// converts 65536 floats starting at element base (base is float4-aligned)
__device__ void conv_chunk(const float* __restrict__ src,
                           bf16* __restrict__ dh, bf16* __restrict__ dl,
                           size_t base, int tid) {
    const float4* s4 = (const float4*)(src + base);
    uint2* h2 = (uint2*)(dh + base);
    uint2* l2 = (uint2*)(dl + base);
    #pragma unroll 4
    for (int i = tid; i < 16384; i += 256) {
        float4 v = s4[i];
        float hx = __bfloat162float(__float2bfloat16(v.x));
        float hy = __bfloat162float(__float2bfloat16(v.y));
        float hz = __bfloat162float(__float2bfloat16(v.z));
        float hw = __bfloat162float(__float2bfloat16(v.w));
        h2[i] = make_uint2(pack2(v.x, v.y), pack2(v.z, v.w));
        l2[i] = make_uint2(pack2(v.x - hx, v.y - hy), pack2(v.z - hz, v.w - hw));
    }
}

// ---------------- GEMM tile (128m x 256n, BK=64, fused hi/lo planes) ----------
// A: K-major planes (x or h). B: row-major [K][N] weight planes via ldmatrix.trans.
// acc += Ah*Bh + Ah*Bl + Al*Bh  (lo*lo dropped)
template <bool FFN1>
__device__ void gemm_tile(char* smem, uint32_t sbase, int e, int m0, int n0,
                          int cnt, int off, const float* __restrict__ b1) {
    constexpr int KTOT = FFN1 ? Dd : Hh;    // A row length (K)
    constexpr int NTOT = FFN1 ? Hh : Dd;    // B row length (N)
    constexpr int NCH  = KTOT / 64;

    int tid = threadIdx.x, wid = tid >> 5, lid = tid & 31;
    int wr = wid & 3, wc = wid >> 2;        // warp tile rows wr*32, cols wc*128

    int* toks = (int*)smem;
    if (FFN1 && tid < 128) {
        int m = m0 + tid;
        toks[tid] = (m < cnt) ? g_tok[e * Tt + m] : -1;
    }
    __syncthreads();

    const bf16* aph; const bf16* apl;
    const bf16* bph; const bf16* bpl;
    if (FFN1) {
        aph = g_xh;  apl = g_xl;
        bph = g_w1h + (size_t)e * Dd * Hh;
        bpl = g_w1l + (size_t)e * Dd * Hh;
    } else {
        aph = g_hh;  apl = g_hl;
        bph = g_w2h + (size_t)e * Hh * Dd;
        bpl = g_w2l + (size_t)e * Hh * Dd;
    }

    auto load_stage = [&](int s, int st) {
        int k0 = s * 64;
        // A planes: 128 rows x 8 chunks, 4 chunks/thread per plane
        #pragma unroll
        for (int i = 0; i < 4; i++) {
            int idx = tid + i * 256;
            int row = idx >> 3, ch = idx & 7;
            int sz = 16;
            size_t goff;
            if (FFN1) {
                int tok = toks[row];
                if (tok < 0) { sz = 0; tok = 0; }
                goff = (size_t)tok * KTOT + k0 + ch * 8;
            } else {
                int m = m0 + row;
                if (m >= cnt) { sz = 0; m = 0; }
                goff = (size_t)(off + m) * KTOT + k0 + ch * 8;
            }
            uint32_t so = swA(row, ch);
            cp16(sbase + SM_AH(st) + so, aph + goff, sz);
            cp16(sbase + SM_AL(st) + so, apl + goff, sz);
        }
        // B planes: 64 rows x 32 chunks (row-major), 8 chunks/thread per plane
        #pragma unroll
        for (int i = 0; i < 8; i++) {
            int idx = tid + i * 256;
            int row = idx >> 5, ch = idx & 31;
            size_t goff = (size_t)(k0 + row) * NTOT + n0 + ch * 8;
            uint32_t so = swB(row, ch);
            cp16(sbase + SM_BH(st) + so, bph + goff, 16);
            cp16(sbase + SM_BL(st) + so, bpl + goff, 16);
        }
        cp_commit();
    };

    float acc[2][16][4];
    #pragma unroll
    for (int i = 0; i < 2; i++)
        #pragma unroll
        for (int j = 0; j < 16; j++)
            #pragma unroll
            for (int q = 0; q < 4; q++) acc[i][j][q] = 0.0f;

    load_stage(0, 0);

    for (int s = 0; s < NCH; s++) {
        int st = s & 1;
        if (s + 1 < NCH) { load_stage(s + 1, st ^ 1); cp_wait1(); }
        else             { cp_wait0(); }
        __syncthreads();

        uint32_t aH = sbase + SM_AH(st), aL = sbase + SM_AL(st);
        uint32_t bH = sbase + SM_BH(st), bL = sbase + SM_BL(st);
        #pragma unroll
        for (int kk = 0; kk < 4; kk++) {
            uint32_t ah[2][4], al[2][4];
            #pragma unroll
            for (int i = 0; i < 2; i++) {
                int row = wr * 32 + i * 16 + (lid & 15);
                int ch  = kk * 2 + (lid >> 4);
                uint32_t so = swA(row, ch);
                ldsm4(ah[i], aH + so);
                ldsm4(al[i], aL + so);
            }
            // B: trans-ldmatrix from row-major; lanes: 0-7 k0-7/c0, 8-15 k8-15/c0,
            // 16-23 k0-7/c1, 24-31 k8-15/c1  -> r0,r1 = n8 frag, r2,r3 = next n8
            int krow = kk * 16 + (lid & 7) + ((lid >> 3) & 1) * 8;
            #pragma unroll
            for (int j2 = 0; j2 < 8; j2++) {
                int ch = wc * 16 + j2 * 2 + (lid >> 4);
                uint32_t so = swB(krow, ch);
                uint32_t bh[4];
                ldsm4t(bh, bH + so);
                mma16816(acc[0][j2 * 2],     ah[0], bh);
                mma16816(acc[1][j2 * 2],     ah[1], bh);
                mma16816(acc[0][j2 * 2 + 1], ah[0], bh + 2);
                mma16816(acc[1][j2 * 2 + 1], ah[1], bh + 2);
                mma16816(acc[0][j2 * 2],     al[0], bh);
                mma16816(acc[1][j2 * 2],     al[1], bh);
                mma16816(acc[0][j2 * 2 + 1], al[0], bh + 2);
                mma16816(acc[1][j2 * 2 + 1], al[1], bh + 2);
                uint32_t bl[4];
                ldsm4t(bl, bL + so);
                mma16816(acc[0][j2 * 2],     ah[0], bl);
                mma16816(acc[1][j2 * 2],     ah[1], bl);
                mma16816(acc[0][j2 * 2 + 1], ah[0], bl + 2);
                mma16816(acc[1][j2 * 2 + 1], ah[1], bl + 2);
            }
        }
        __syncthreads();
    }

    // -------- epilogue --------
    #pragma unroll
    for (int i = 0; i < 2; i++) {
        #pragma unroll
        for (int rh = 0; rh < 2; rh++) {
            int m = m0 + wr * 32 + i * 16 + rh * 8 + (lid >> 2);
            if (m >= cnt) continue;
            #pragma unroll
            for (int j = 0; j < 16; j++) {
                int n = n0 + wc * 128 + j * 8 + (lid & 3) * 2;
                float v0 = acc[i][j][rh * 2 + 0];
                float v1 = acc[i][j][rh * 2 + 1];
                if (FFN1) {
                    const float* b1p = b1 + (size_t)e * Hh + n;
                    v0 = fmaxf(v0 + b1p[0], 0.f);
                    v1 = fmaxf(v1 + b1p[1], 0.f);
                    float h0 = __bfloat162float(__float2bfloat16(v0));
                    float h1 = __bfloat162float(__float2bfloat16(v1));
                    size_t base = (size_t)(off + m) * Hh + n;
                    *(unsigned*)(g_hh + base) = pack2(v0, v1);
                    *(unsigned*)(g_hl + base) = pack2(v0 - h0, v1 - h1);
                } else {
                    size_t base = (size_t)(off + m) * Dd + n;
                    *(float2*)(g_y + base) = make_float2(v0, v1);
                }
            }
        }
    }
}

// ---------------- persistent worker -------------------------------------------
__global__ __launch_bounds__(256, 1)
void moe_persistent_kernel(const float* __restrict__ x,
                           const float* __restrict__ w1,
                           const float* __restrict__ w2,
                           const float* __restrict__ b1) {
    extern __shared__ __align__(1024) char smem[];
    uint32_t sbase = smem_u32(smem);
    int tid = threadIdx.x;
    __shared__ int s_t;

    for (;;) {
        if (tid == 0) s_t = atomicAdd(&g_ticket, 1);
        __syncthreads();
        int t = s_t;
        __syncthreads();
        if (t >= TEND) break;

        if (t < TB1) {
            // conv x
            conv_chunk(x, g_xh, g_xl, (size_t)t * 65536, tid);
            __threadfence();
            __syncthreads();
            if (tid == 0) atomicAdd(&c_x, 1);
        } else if (t < TB2) {
            // conv w1 (expert-major tickets; layout contiguous)
            int i = t - TB1;
            conv_chunk(w1, g_w1h, g_w1l, (size_t)i * 65536, tid);
            __threadfence();
            __syncthreads();
            if (tid == 0) atomicAdd(&c_w1[i >> 5], 1);
        } else if (t < TB3) {
            // conv w2
            int i = t - TB2;
            conv_chunk(w2, g_w2h, g_w2l, (size_t)i * 65536, tid);
            __threadfence();
            __syncthreads();
            if (tid == 0) atomicAdd(&c_w2[i >> 5], 1);
        } else if (t < TB4) {
            // FFN1 tile
            int i = t - TB3;
            int e  = i / (MBMAX * NB1);
            int r  = i % (MBMAX * NB1);
            int mb = r / NB1, nb = r % NB1;
            int cnt = g_count[e];
            if (mb * 128 < cnt) {
                if (tid == 0) {
                    while (ldacq(&c_x) < TCX) {}
                    while (ldacq(&c_w1[e]) < TW1E) {}
                }
                __syncthreads();
                gemm_tile<true>(smem, sbase, e, mb * 128, nb * 256,
                                cnt, g_off[e], b1);
                __threadfence();
                __syncthreads();
                if (tid == 0) atomicAdd(&c_h[e * MBMAX + mb], 1);
            }
        } else {
            // FFN2 tile
            int i = t - TB4;
            int e  = i / (MBMAX * NB2);
            int r  = i % (MBMAX * NB2);
            int mb = r / NB2, nb = r % NB2;
            int cnt = g_count[e];
            if (mb * 128 < cnt) {
                if (tid == 0) {
                    while (ldacq(&c_w2[e]) < TW2E) {}
                    while (ldacq(&c_h[e * MBMAX + mb]) < NB1) {}
                }
                __syncthreads();
                gemm_tile<false>(smem, sbase, e, mb * 128, nb * 256,
                                 cnt, g_off[e], b1);
                __syncthreads();
            }
        }
    }
}

// ---------------- combine: out[t] = g0*(y0+b2[e0]) + g1*(y1+b2[e1]) ----------
__global__ void combine_kernel(const float* __restrict__ b2,
                               float* __restrict__ out) {
    int t   = blockIdx.x;
    int tid = threadIdx.x;                    // 256 threads * float4 = 1024 = Dd
    int e0 = g_eidx[t * Kk + 0], e1 = g_eidx[t * Kk + 1];
    int s0 = g_off[e0] + g_pos[t * Kk + 0];
    int s1 = g_off[e1] + g_pos[t * Kk + 1];
    float g0 = g_gatev[t * Kk + 0], g1 = g_gatev[t * Kk + 1];

    const float4* y0 = (const float4*)(g_y + (size_t)s0 * Dd);
    const float4* y1 = (const float4*)(g_y + (size_t)s1 * Dd);
    const float4* c0 = (const float4*)(b2 + (size_t)e0 * Dd);
    const float4* c1 = (const float4*)(b2 + (size_t)e1 * Dd);
    float4* o = (float4*)(out + (size_t)t * Dd);

    float4 a = y0[tid], b = y1[tid], p = c0[tid], q = c1[tid];
    float4 r;
    r.x = g0 * (a.x + p.x) + g1 * (b.x + q.x);
    r.y = g0 * (a.y + p.y) + g1 * (b.y + q.y);
    r.z = g0 * (a.z + p.z) + g1 * (b.z + q.z);
    r.w = g0 * (a.w + p.w) + g1 * (b.w + q.w);
    o[tid] = r;
}

__global__ void ent_kernel(float* __restrict__ out, int out_size) {
    if (out_size > Tt * Dd)
        out[Tt * Dd] = g_ent / (float)Tt;
}

// ---------------- launch ------------------------------------------------------
extern "C" void kernel_launch(void* const* d_in, const int* in_sizes, int n_in,
                              void* d_out, int out_size) {
    const float* x  = (const float*)d_in[0];
    const float* wg = (const float*)d_in[1];
    const float* bg = (const float*)d_in[2];
    const float* w1 = (const float*)d_in[3];
    const float* b1 = (const float*)d_in[4];
    const float* w2 = (const float*)d_in[5];
    const float* b2 = (const float*)d_in[6];
    float* out = (float*)d_out;

    cudaFuncSetAttribute(moe_persistent_kernel,
                         cudaFuncAttributeMaxDynamicSharedMemorySize, MMA_SMEM_BYTES);

    reset_kernel<<<1, 512>>>();
    gate_kernel<<<Tt / 8, 256>>>(x, wg, bg);
    offs_kernel<<<1, 32>>>();

    moe_persistent_kernel<<<148, 256, MMA_SMEM_BYTES>>>(x, w1, w2, b1);

    combine_kernel<<<Tt, 256>>>(b2, out);
    ent_kernel<<<1, 1>>>(out, out_size);
}

// round 16
// speedup vs baseline: 1.0474x; 1.0474x over previous
#include <cuda_runtime.h>
#include <cuda_bf16.h>
#include <math.h>
#include <stdint.h>

typedef __nv_bfloat16 bf16;

// Problem constants
#define Bb 2
#define Nn 2048
#define Dd 1024
#define Ee 8
#define Hh 2048
#define Kk 2
#define Tt (Bb*Nn)              // 4096 tokens
#define SLOTS (Tt*Kk)           // 8192

// ---------------- routing state ----------------------------------------------
__device__ int   g_count[Ee];
__device__ int   g_off[Ee];
__device__ float g_ent;
__device__ int   g_tok[Ee * Tt];
__device__ int   g_pos[Tt * Kk];
__device__ int   g_eidx[Tt * Kk];
__device__ float g_gatev[Tt * Kk];
__device__ int   g_t1, g_t2;          // GEMM tile tickets

// ---------------- bf16 split planes (weights in ORIGINAL row-major layout) ---
__device__ bf16  g_xh[(size_t)Tt * Dd],      g_xl[(size_t)Tt * Dd];
__device__ bf16  g_w1h[(size_t)Ee * Dd * Hh], g_w1l[(size_t)Ee * Dd * Hh]; // [E][D][H]
__device__ bf16  g_w2h[(size_t)Ee * Hh * Dd], g_w2l[(size_t)Ee * Hh * Dd]; // [E][H][D]
__device__ bf16  g_hh[(size_t)SLOTS * Hh],   g_hl[(size_t)SLOTS * Hh];
__device__ float g_y[(size_t)SLOTS * Dd];

#define MBMAX 32
#define NB1 (Hh/256)            // 8
#define NB2 (Dd/256)            // 4
#define TOT1 (Ee*MBMAX*NB1)     // 2048
#define TOT2 (Ee*MBMAX*NB2)     // 1024

// ============================ PTX helpers ====================================
__device__ __forceinline__ uint32_t smem_u32(const void* p) {
    uint32_t a;
    asm("{ .reg .u64 t; cvta.to.shared.u64 t, %1; cvt.u32.u64 %0, t; }"
        : "=r"(a) : "l"(p));
    return a;
}
__device__ __forceinline__ void cp16(uint32_t dst, const void* src, int sz) {
    asm volatile("cp.async.cg.shared.global [%0], [%1], 16, %2;"
                 :: "r"(dst), "l"(src), "r"(sz) : "memory");
}
__device__ __forceinline__ void cp_commit() {
    asm volatile("cp.async.commit_group;" ::: "memory");
}
__device__ __forceinline__ void cp_wait1() {
    asm volatile("cp.async.wait_group 1;" ::: "memory");
}
__device__ __forceinline__ void cp_wait0() {
    asm volatile("cp.async.wait_group 0;" ::: "memory");
}
__device__ __forceinline__ void ldsm4(uint32_t* r, uint32_t addr) {
    asm volatile("ldmatrix.sync.aligned.m8n8.x4.shared.b16 {%0,%1,%2,%3}, [%4];"
                 : "=r"(r[0]), "=r"(r[1]), "=r"(r[2]), "=r"(r[3]) : "r"(addr));
}
__device__ __forceinline__ void ldsm4t(uint32_t* r, uint32_t addr) {
    asm volatile("ldmatrix.sync.aligned.m8n8.x4.trans.shared.b16 {%0,%1,%2,%3}, [%4];"
                 : "=r"(r[0]), "=r"(r[1]), "=r"(r[2]), "=r"(r[3]) : "r"(addr));
}
__device__ __forceinline__ void mma16816(float* c, const uint32_t* a, const uint32_t* b) {
    asm volatile(
        "mma.sync.aligned.m16n8k16.row.col.f32.bf16.bf16.f32 "
        "{%0,%1,%2,%3}, {%4,%5,%6,%7}, {%8,%9}, {%0,%1,%2,%3};"
        : "+f"(c[0]), "+f"(c[1]), "+f"(c[2]), "+f"(c[3])
        : "r"(a[0]), "r"(a[1]), "r"(a[2]), "r"(a[3]), "r"(b[0]), "r"(b[1]));
}

// A smem tile: 128 rows x 8 chunks of 16B (64 bf16/row), XOR-swizzled
__device__ __forceinline__ uint32_t swA(int row, int ch) {
    return (uint32_t)((row * 8 + (ch ^ (row & 7))) << 4);
}
// B smem tile (row-major K x N): 64 rows x 32 chunks of 16B (256 bf16/row)
__device__ __forceinline__ uint32_t swB(int row, int ch) {
    return (uint32_t)((row * 32 + ((ch & 24) | ((ch ^ row) & 7))) << 4);
}

// dynamic smem: [0,512) toks; per stage 96KB = AH 16K | AL 16K | BH 32K | BL 32K
#define SM_AH(st) (1024 + (st) * 98304)
#define SM_AL(st) (1024 + (st) * 98304 + 16384)
#define SM_BH(st) (1024 + (st) * 98304 + 32768)
#define SM_BL(st) (1024 + (st) * 98304 + 65536)
#define MMA_SMEM_BYTES (1024 + 2 * 98304)   // 197632

#define NT 512   // threads per GEMM CTA

// ---------------- reset -------------------------------------------------------
__global__ void reset_kernel() {
    int i = threadIdx.x;
    if (i < Ee) g_count[i] = 0;
    if (i == 0) { g_ent = 0.0f; g_t1 = 0; g_t2 = 0; }
}

// ---------------- gating: one warp per token ---------------------------------
__global__ __launch_bounds__(256)
void gate_kernel(const float* __restrict__ x,
                 const float* __restrict__ wg,
                 const float* __restrict__ bg) {
    int t    = (blockIdx.x * blockDim.x + threadIdx.x) >> 5;
    int lane = threadIdx.x & 31;
    if (t >= Tt) return;

    const float* xr = x + (size_t)t * Dd;
    float acc[Ee];
    #pragma unroll
    for (int e = 0; e < Ee; e++) acc[e] = 0.0f;

    for (int d = lane; d < Dd; d += 32) {
        float xv = xr[d];
        const float4* w4 = (const float4*)(wg + (size_t)d * Ee);
        float4 a = w4[0], b = w4[1];
        acc[0] += xv * a.x; acc[1] += xv * a.y; acc[2] += xv * a.z; acc[3] += xv * a.w;
        acc[4] += xv * b.x; acc[5] += xv * b.y; acc[6] += xv * b.z; acc[7] += xv * b.w;
    }
    #pragma unroll
    for (int e = 0; e < Ee; e++) {
        #pragma unroll
        for (int off = 16; off; off >>= 1)
            acc[e] += __shfl_xor_sync(0xffffffffu, acc[e], off);
    }

    if (lane == 0) {
        float best0 = -INFINITY, best1 = -INFINITY;
        int i0 = 0, i1 = 0;
        #pragma unroll
        for (int e = 0; e < Ee; e++) {
            float l = acc[e] + bg[e];
            if (l > best0)      { best1 = best0; i1 = i0; best0 = l; i0 = e; }
            else if (l > best1) { best1 = l; i1 = e; }
        }
        float ex = expf(best1 - best0);
        float g0 = 1.0f / (1.0f + ex);
        float g1 = ex * g0;
        float ent = -(g0 * logf(fmaxf(g0, 1e-8f)) + g1 * logf(fmaxf(g1, 1e-8f)));
        atomicAdd(&g_ent, ent);

        int p0 = atomicAdd(&g_count[i0], 1);
        g_tok[i0 * Tt + p0] = t;
        g_pos[t * Kk + 0]   = p0;
        g_gatev[t * Kk + 0] = g0;
        g_eidx[t * Kk + 0]  = i0;

        int p1 = atomicAdd(&g_count[i1], 1);
        g_tok[i1 * Tt + p1] = t;
        g_pos[t * Kk + 1]   = p1;
        g_gatev[t * Kk + 1] = g1;
        g_eidx[t * Kk + 1]  = i1;
    }
}

__global__ void offs_kernel() {
    if (threadIdx.x == 0) {
        int a = 0;
        #pragma unroll
        for (int e = 0; e < Ee; e++) { g_off[e] = a; a += g_count[e]; }
    }
}

// ---------------- streaming fp32 -> bf16 hi/lo split --------------------------
// NOTE: destinations are __device__ globals selected IN DEVICE CODE (passing
// a __device__ symbol as a host-side kernel argument is invalid — R13/R14 bug).
__device__ __forceinline__ unsigned pack2(float a, float b) {
    bf16 ha = __float2bfloat16(a), hb = __float2bfloat16(b);
    return (unsigned)__bfloat16_as_ushort(ha)
         | ((unsigned)__bfloat16_as_ushort(hb) << 16);
}

// 256 threads, 4 float4 per thread -> 1024 float4 (4096 floats) per block
__global__ __launch_bounds__(256)
void conv_split_kernel(const float* __restrict__ src, int which) {
    bf16* dh; bf16* dl;
    if (which == 0)      { dh = g_xh;  dl = g_xl;  }
    else if (which == 1) { dh = g_w1h; dl = g_w1l; }
    else                 { dh = g_w2h; dl = g_w2l; }

    size_t base = (size_t)blockIdx.x * 1024;
    const float4* s4 = (const float4*)src + base;
    uint2* h2 = (uint2*)dh + base;
    uint2* l2 = (uint2*)dl + base;
    float4 v[4];
    #pragma unroll
    for (int i = 0; i < 4; i++) v[i] = s4[threadIdx.x + i * 256];
    #pragma unroll
    for (int i = 0; i < 4; i++) {
        float hx = __bfloat162float(__float2bfloat16(v[i].x));
        float hy = __bfloat162float(__float2bfloat16(v[i].y));
        float hz = __bfloat162float(__float2bfloat16(v[i].z));
        float hw = __bfloat162float(__float2bfloat16(v[i].w));
        h2[threadIdx.x + i * 256] =
            make_uint2(pack2(v[i].x, v[i].y), pack2(v[i].z, v[i].w));
        l2[threadIdx.x + i * 256] =
            make_uint2(pack2(v[i].x - hx, v[i].y - hy), pack2(v[i].z - hz, v[i].w - hw));
    }
}

// ---------------- GEMM tile body (128m x 256n, BK=64, fused hi/lo) ------------
// 16 warps, warp grid 4(m) x 4(n), warp tile 32m x 64n.
// A: K-major planes. B: row-major [K][N] via ldmatrix.trans.
// acc += Ah*Bh + Ah*Bl + Al*Bh.
template <bool FFN1>
__device__ __forceinline__ void gemm_tile(char* smem, uint32_t sbase,
                                          int e, int m0, int n0, int cnt, int off,
                                          const float* __restrict__ b1) {
    constexpr int KTOT = FFN1 ? Dd : Hh;
    constexpr int NTOT = FFN1 ? Hh : Dd;
    constexpr int NCH  = KTOT / 64;

    int tid = threadIdx.x, wid = tid >> 5, lid = tid & 31;
    int wr = wid & 3, wc = wid >> 2;        // rows wr*32, cols wc*64

    int* toks = (int*)smem;
    if (FFN1 && tid < 128) {
        int m = m0 + tid;
        toks[tid] = (m < cnt) ? g_tok[e * Tt + m] : -1;
    }
    __syncthreads();

    const bf16* aph; const bf16* apl;
    const bf16* bph; const bf16* bpl;
    if (FFN1) {
        aph = g_xh;  apl = g_xl;
        bph = g_w1h + (size_t)e * Dd * Hh;
        bpl = g_w1l + (size_t)e * Dd * Hh;
    } else {
        aph = g_hh;  apl = g_hl;
        bph = g_w2h + (size_t)e * Hh * Dd;
        bpl = g_w2l + (size_t)e * Hh * Dd;
    }

    auto load_stage = [&](int s, int st) {
        int k0 = s * 64;
        // A planes: 1024 chunks each, 2/thread
        #pragma unroll
        for (int i = 0; i < 2; i++) {
            int idx = tid + i * NT;
            int row = idx >> 3, ch = idx & 7;
            int sz = 16;
            size_t goff;
            if (FFN1) {
                int tok = toks[row];
                if (tok < 0) { sz = 0; tok = 0; }
                goff = (size_t)tok * KTOT + k0 + ch * 8;
            } else {
                int m = m0 + row;
                if (m >= cnt) { sz = 0; m = 0; }
                goff = (size_t)(off + m) * KTOT + k0 + ch * 8;
            }
            uint32_t so = swA(row, ch);
            cp16(sbase + SM_AH(st) + so, aph + goff, sz);
            cp16(sbase + SM_AL(st) + so, apl + goff, sz);
        }
        // B planes: 2048 chunks each, 4/thread
        #pragma unroll
        for (int i = 0; i < 4; i++) {
            int idx = tid + i * NT;
            int row = idx >> 5, ch = idx & 31;
            size_t goff = (size_t)(k0 + row) * NTOT + n0 + ch * 8;
            uint32_t so = swB(row, ch);
            cp16(sbase + SM_BH(st) + so, bph + goff, 16);
            cp16(sbase + SM_BL(st) + so, bpl + goff, 16);
        }
        cp_commit();
    };

    float acc[2][8][4];
    #pragma unroll
    for (int i = 0; i < 2; i++)
        #pragma unroll
        for (int j = 0; j < 8; j++)
            #pragma unroll
            for (int q = 0; q < 4; q++) acc[i][j][q] = 0.0f;

    load_stage(0, 0);

    for (int s = 0; s < NCH; s++) {
        int st = s & 1;
        if (s + 1 < NCH) { load_stage(s + 1, st ^ 1); cp_wait1(); }
        else             { cp_wait0(); }
        __syncthreads();

        uint32_t aH = sbase + SM_AH(st), aL = sbase + SM_AL(st);
        uint32_t bH = sbase + SM_BH(st), bL = sbase + SM_BL(st);
        #pragma unroll
        for (int kk = 0; kk < 4; kk++) {
            uint32_t ah[2][4], al[2][4];
            #pragma unroll
            for (int i = 0; i < 2; i++) {
                int row = wr * 32 + i * 16 + (lid & 15);
                int ch  = kk * 2 + (lid >> 4);
                uint32_t so = swA(row, ch);
                ldsm4(ah[i], aH + so);
                ldsm4(al[i], aL + so);
            }
            int krow = kk * 16 + (lid & 7) + ((lid >> 3) & 1) * 8;
            #pragma unroll
            for (int j2 = 0; j2 < 4; j2++) {
                int ch = wc * 8 + j2 * 2 + (lid >> 4);
                uint32_t so = swB(krow, ch);
                uint32_t bh[4];
                ldsm4t(bh, bH + so);
                mma16816(acc[0][j2 * 2],     ah[0], bh);
                mma16816(acc[1][j2 * 2],     ah[1], bh);
                mma16816(acc[0][j2 * 2 + 1], ah[0], bh + 2);
                mma16816(acc[1][j2 * 2 + 1], ah[1], bh + 2);
                mma16816(acc[0][j2 * 2],     al[0], bh);
                mma16816(acc[1][j2 * 2],     al[1], bh);
                mma16816(acc[0][j2 * 2 + 1], al[0], bh + 2);
                mma16816(acc[1][j2 * 2 + 1], al[1], bh + 2);
                uint32_t bl[4];
                ldsm4t(bl, bL + so);
                mma16816(acc[0][j2 * 2],     ah[0], bl);
                mma16816(acc[1][j2 * 2],     ah[1], bl);
                mma16816(acc[0][j2 * 2 + 1], ah[0], bl + 2);
                mma16816(acc[1][j2 * 2 + 1], ah[1], bl + 2);
            }
        }
        __syncthreads();
    }

    // -------- epilogue --------
    #pragma unroll
    for (int i = 0; i < 2; i++) {
        #pragma unroll
        for (int rh = 0; rh < 2; rh++) {
            int m = m0 + wr * 32 + i * 16 + rh * 8 + (lid >> 2);
            if (m >= cnt) continue;
            #pragma unroll
            for (int j = 0; j < 8; j++) {
                int n = n0 + wc * 64 + j * 8 + (lid & 3) * 2;
                float v0 = acc[i][j][rh * 2 + 0];
                float v1 = acc[i][j][rh * 2 + 1];
                if (FFN1) {
                    const float* b1p = b1 + (size_t)e * Hh + n;
                    v0 = fmaxf(v0 + b1p[0], 0.f);
                    v1 = fmaxf(v1 + b1p[1], 0.f);
                    float h0 = __bfloat162float(__float2bfloat16(v0));
                    float h1 = __bfloat162float(__float2bfloat16(v1));
                    size_t base = (size_t)(off + m) * Hh + n;
                    *(unsigned*)(g_hh + base) = pack2(v0, v1);
                    *(unsigned*)(g_hl + base) = pack2(v0 - h0, v1 - h1);
                } else {
                    size_t base = (size_t)(off + m) * Dd + n;
                    *(float2*)(g_y + base) = make_float2(v0, v1);
                }
            }
        }
    }
}

// ---------------- persistent GEMM kernels (ticket per tile) -------------------
__global__ __launch_bounds__(NT, 1)
void ffn1_kernel(const float* __restrict__ b1) {
    extern __shared__ __align__(1024) char smem[];
    uint32_t sbase = smem_u32(smem);
    __shared__ int s_t;
    for (;;) {
        if (threadIdx.x == 0) s_t = atomicAdd(&g_t1, 1);
        __syncthreads();
        int t = s_t;
        __syncthreads();
        if (t >= TOT1) break;
        int e  = t / (MBMAX * NB1);
        int r  = t % (MBMAX * NB1);
        int mb = r / NB1, nb = r % NB1;
        int cnt = g_count[e];
        if (mb * 128 >= cnt) continue;
        gemm_tile<true>(smem, sbase, e, mb * 128, nb * 256, cnt, g_off[e], b1);
        __syncthreads();
    }
}

__global__ __launch_bounds__(NT, 1)
void ffn2_kernel() {
    extern __shared__ __align__(1024) char smem[];
    uint32_t sbase = smem_u32(smem);
    __shared__ int s_t;
    for (;;) {
        if (threadIdx.x == 0) s_t = atomicAdd(&g_t2, 1);
        __syncthreads();
        int t = s_t;
        __syncthreads();
        if (t >= TOT2) break;
        int e  = t / (MBMAX * NB2);
        int r  = t % (MBMAX * NB2);
        int mb = r / NB2, nb = r % NB2;
        int cnt = g_count[e];
        if (mb * 128 >= cnt) continue;
        gemm_tile<false>(smem, sbase, e, mb * 128, nb * 256, cnt, g_off[e], nullptr);
        __syncthreads();
    }
}

// ---------------- combine: out[t] = g0*(y0+b2[e0]) + g1*(y1+b2[e1]) ----------
__global__ __launch_bounds__(256)
void combine_kernel(const float* __restrict__ b2,
                    float* __restrict__ out) {
    int t   = blockIdx.x;
    int tid = threadIdx.x;                    // 256 threads * float4 = 1024 = Dd
    int e0 = g_eidx[t * Kk + 0], e1 = g_eidx[t * Kk + 1];
    int s0 = g_off[e0] + g_pos[t * Kk + 0];
    int s1 = g_off[e1] + g_pos[t * Kk + 1];
    float g0 = g_gatev[t * Kk + 0], g1 = g_gatev[t * Kk + 1];

    const float4* y0 = (const float4*)(g_y + (size_t)s0 * Dd);
    const float4* y1 = (const float4*)(g_y + (size_t)s1 * Dd);
    const float4* c0 = (const float4*)(b2 + (size_t)e0 * Dd);
    const float4* c1 = (const float4*)(b2 + (size_t)e1 * Dd);
    float4* o = (float4*)(out + (size_t)t * Dd);

    float4 a = y0[tid], b = y1[tid], p = c0[tid], q = c1[tid];
    float4 r;
    r.x = g0 * (a.x + p.x) + g1 * (b.x + q.x);
    r.y = g0 * (a.y + p.y) + g1 * (b.y + q.y);
    r.z = g0 * (a.z + p.z) + g1 * (b.z + q.z);
    r.w = g0 * (a.w + p.w) + g1 * (b.w + q.w);
    o[tid] = r;
}

__global__ void ent_kernel(float* __restrict__ out, int out_size) {
    if (out_size > Tt * Dd)
        out[Tt * Dd] = g_ent / (float)Tt;
}

// ---------------- launch ------------------------------------------------------
extern "C" void kernel_launch(void* const* d_in, const int* in_sizes, int n_in,
                              void* d_out, int out_size) {
    const float* x  = (const float*)d_in[0];
    const float* wg = (const float*)d_in[1];
    const float* bg = (const float*)d_in[2];
    const float* w1 = (const float*)d_in[3];
    const float* b1 = (const float*)d_in[4];
    const float* w2 = (const float*)d_in[5];
    const float* b2 = (const float*)d_in[6];
    float* out = (float*)d_out;

    cudaFuncSetAttribute(ffn1_kernel,
                         cudaFuncAttributeMaxDynamicSharedMemorySize, MMA_SMEM_BYTES);
    cudaFuncSetAttribute(ffn2_kernel,
                         cudaFuncAttributeMaxDynamicSharedMemorySize, MMA_SMEM_BYTES);

    reset_kernel<<<1, 32>>>();
    gate_kernel<<<Tt / 8, 256>>>(x, wg, bg);
    offs_kernel<<<1, 32>>>();

    // conversions: each block covers 1024 float4 = 4096 floats
    conv_split_kernel<<<(Tt * Dd) / 4096, 256>>>(x, 0);
    conv_split_kernel<<<(Ee * Dd * Hh) / 4096, 256>>>(w1, 1);
    conv_split_kernel<<<(Ee * Hh * Dd) / 4096, 256>>>(w2, 2);

    ffn1_kernel<<<148, NT, MMA_SMEM_BYTES>>>(b1);
    ffn2_kernel<<<148, NT, MMA_SMEM_BYTES>>>();

    combine_kernel<<<Tt, 256>>>(b2, out);
    ent_kernel<<<1, 1>>>(out, out_size);
}